// round 16
// baseline (speedup 1.0000x reference)
#include <cuda_runtime.h>
#include <math_constants.h>

#define HID   64
#define MAXN  50000

// Per-node precomputed tables, stride 8 floats for float4 alignment.
// srcTab[n*8 + 0..3] = ps (x0·Wsp + bsp), [n*8+4] = gs (x·Wsg + bsg)
// dstTab[n*8 + 0..3] = pd (x0·Wdp),       [n*8+4] = gd (x·Wdg + bdg)
__device__ float g_srcTab[MAXN * 8];
__device__ float g_dstTab[MAXN * 8];

// 8 lanes per node; smem-staged weights; butterfly transpose-reduce;
// distributed stores. Also zeroes the output accumulators.
__global__ void __launch_bounds__(256)
node_kernel(const float* __restrict__ x,
            const float* __restrict__ x0,
            const float* __restrict__ Wsg, const float* __restrict__ bsg,
            const float* __restrict__ Wdg, const float* __restrict__ bdg,
            const float* __restrict__ Wsp, const float* __restrict__ bsp,
            const float* __restrict__ Wdp,
            float* __restrict__ atom, float* __restrict__ out0,
            int n)
{
    __shared__ float sWsp[HID * 4];
    __shared__ float sWdp[HID * 4];
    __shared__ float sWsg[HID];
    __shared__ float sWdg[HID];

    const int tid = threadIdx.x;
    sWsp[tid] = Wsp[tid];
    sWdp[tid] = Wdp[tid];
    if (tid < HID) { sWsg[tid] = Wsg[tid]; sWdg[tid] = Wdg[tid]; }
    __syncthreads();

    int t    = blockIdx.x * blockDim.x + tid;
    int node = t >> 3;
    int sub  = t & 7;
    if (node >= n) return;

    const size_t base = (size_t)node * HID;
    const int h0 = sub * 4;
    const int h1 = 32 + sub * 4;

    float4 xa  = *(const float4*)(x  + base + h0);
    float4 xb  = *(const float4*)(x  + base + h1);
    float4 x0a = *(const float4*)(x0 + base + h0);
    float4 x0b = *(const float4*)(x0 + base + h1);

    float gs = 0.f, gd = 0.f;
    float v[8];
#pragma unroll
    for (int p = 0; p < 8; p++) v[p] = 0.f;

    const float* xav  = (const float*)&xa;
    const float* xbv  = (const float*)&xb;
    const float* x0av = (const float*)&x0a;
    const float* x0bv = (const float*)&x0b;

#pragma unroll
    for (int k = 0; k < 4; k++) {
        int ha = h0 + k, hb = h1 + k;
        gs += xav[k] * sWsg[ha] + xbv[k] * sWsg[hb];
        gd += xav[k] * sWdg[ha] + xbv[k] * sWdg[hb];
        float4 wsa = *(const float4*)(sWsp + ha * 4);
        float4 wsb = *(const float4*)(sWsp + hb * 4);
        float4 wda = *(const float4*)(sWdp + ha * 4);
        float4 wdb = *(const float4*)(sWdp + hb * 4);
        v[0] += x0av[k] * wsa.x + x0bv[k] * wsb.x;
        v[1] += x0av[k] * wsa.y + x0bv[k] * wsb.y;
        v[2] += x0av[k] * wsa.z + x0bv[k] * wsb.z;
        v[3] += x0av[k] * wsa.w + x0bv[k] * wsb.w;
        v[4] += x0av[k] * wda.x + x0bv[k] * wdb.x;
        v[5] += x0av[k] * wda.y + x0bv[k] * wdb.y;
        v[6] += x0av[k] * wda.z + x0bv[k] * wdb.z;
        v[7] += x0av[k] * wda.w + x0bv[k] * wdb.w;
    }

    bool hi4 = (sub & 4) != 0;
    float a0k = hi4 ? v[4] : v[0], a0s = hi4 ? v[0] : v[4];
    float a1k = hi4 ? v[5] : v[1], a1s = hi4 ? v[1] : v[5];
    float a2k = hi4 ? v[6] : v[2], a2s = hi4 ? v[2] : v[6];
    float a3k = hi4 ? v[7] : v[3], a3s = hi4 ? v[3] : v[7];
    a0k += __shfl_xor_sync(0xffffffffu, a0s, 4);
    a1k += __shfl_xor_sync(0xffffffffu, a1s, 4);
    a2k += __shfl_xor_sync(0xffffffffu, a2s, 4);
    a3k += __shfl_xor_sync(0xffffffffu, a3s, 4);
    bool hi2 = (sub & 2) != 0;
    float b0k = hi2 ? a2k : a0k, b0s = hi2 ? a0k : a2k;
    float b1k = hi2 ? a3k : a1k, b1s = hi2 ? a1k : a3k;
    b0k += __shfl_xor_sync(0xffffffffu, b0s, 2);
    b1k += __shfl_xor_sync(0xffffffffu, b1s, 2);
    bool hi1 = (sub & 1) != 0;
    float ck = hi1 ? b1k : b0k, cs = hi1 ? b0k : b1k;
    ck += __shfl_xor_sync(0xffffffffu, cs, 1);

#pragma unroll
    for (int off = 4; off >= 1; off >>= 1) {
        gs += __shfl_xor_sync(0xffffffffu, gs, off);
        gd += __shfl_xor_sync(0xffffffffu, gd, off);
    }

    if (sub < 4)
        g_srcTab[(size_t)node * 8 + sub] = ck + __ldg(bsp + sub);
    else
        g_dstTab[(size_t)node * 8 + (sub - 4)] = ck;
    if (sub == 0) {
        g_srcTab[(size_t)node * 8 + 4] = gs + __ldg(bsg);
        g_dstTab[(size_t)node * 8 + 4] = gd + __ldg(bdg);
        atom[node] = 0.0f;
        if (node == 0) *out0 = 0.0f;
    }
}

// Persistent edge kernel — DENSE STREAM variant. y is loaded unconditionally
// (no cutoff gating on the stream; dot results for dead edges are simply
// unused in the tail). This removes all y-load predicates and the r[]->y
// dependency, so the bond-prefetch pipeline is unnecessary: bond is read
// ONCE per edge via a coalesced __ldcs issued at the top of the iteration,
// arriving long before the tail consumes it. Loop body = pure unconditional
// 16x LDG.128 burst + FMA + 7-shuffle transpose-reduce + self-contained tail.
__global__ void __launch_bounds__(256, 5)
edge_kernel(const float* __restrict__ y,
            const float* __restrict__ bondlength,
            const int* __restrict__ src,
            const int* __restrict__ dst,
            const float* __restrict__ Weg,
            const float* __restrict__ beg,
            float* __restrict__ atom,
            float* __restrict__ out0,
            int E, float invN)
{
    __shared__ float sWeg[HID];
    __shared__ float sEsum;
    int tid = threadIdx.x;
    if (tid < HID) sWeg[tid] = Weg[tid];
    if (tid == 0)  sEsum = 0.0f;
    __syncthreads();

    const int sub      = tid & 7;
    const int grpInBlk = tid >> 3;             // 0..31
    const float4 wa = *(const float4*)(sWeg + sub * 4);
    const float4 wb = *(const float4*)(sWeg + 32 + sub * 4);
    const float begv = __ldg(beg);

    const int CHUNK = 256;                     // edges per block-iteration
    const int nChunks = (E + CHUNK - 1) / CHUNK;

    float Vacc = 0.0f;

    for (int chunk = blockIdx.x; chunk < nChunks; chunk += gridDim.x) {
        const int e0 = chunk * CHUNK + grpInBlk * 8;
        const float* ybase = y + (size_t)e0 * HID;

        // 0) this lane's tail bond length — coalesced, issued before the burst
        int  e   = e0 + sub;
        float myr = (e < E) ? __ldcs(bondlength + e) : 5.0f;

        // 1) UNCONDITIONAL y burst: 8 rows x 2 contiguous 128B lines
        float d[8];
        bool full = (e0 + 8 <= E);
#pragma unroll
        for (int p = 0; p < 8; p++) {
            float da = 0.f;
            if (full || e0 + p < E) {
                const float* row = ybase + (size_t)p * HID;
                float4 a = __ldcs((const float4*)(row + sub * 4));
                float4 b = __ldcs((const float4*)(row + 32 + sub * 4));
                da = a.x*wa.x + a.y*wa.y + a.z*wa.z + a.w*wa.w
                   + b.x*wb.x + b.y*wb.y + b.z*wb.z + b.w*wb.w;
            }
            d[p] = da;
        }

        // 2) transpose-reduce: 7 shuffles; lane sub holds dot of edge e0+sub
        bool hi4 = (sub & 4) != 0;
        float a0k = hi4 ? d[4] : d[0], a0s = hi4 ? d[0] : d[4];
        float a1k = hi4 ? d[5] : d[1], a1s = hi4 ? d[1] : d[5];
        float a2k = hi4 ? d[6] : d[2], a2s = hi4 ? d[2] : d[6];
        float a3k = hi4 ? d[7] : d[3], a3s = hi4 ? d[3] : d[7];
        a0k += __shfl_xor_sync(0xffffffffu, a0s, 4);
        a1k += __shfl_xor_sync(0xffffffffu, a1s, 4);
        a2k += __shfl_xor_sync(0xffffffffu, a2s, 4);
        a3k += __shfl_xor_sync(0xffffffffu, a3s, 4);
        bool hi2 = (sub & 2) != 0;
        float b0k = hi2 ? a2k : a0k, b0s = hi2 ? a0k : a2k;
        float b1k = hi2 ? a3k : a1k, b1s = hi2 ? a1k : a3k;
        b0k += __shfl_xor_sync(0xffffffffu, b0s, 2);
        b1k += __shfl_xor_sync(0xffffffffu, b1s, 2);
        bool hi1 = (sub & 1) != 0;
        float myd = hi1 ? b1k : b0k, cs = hi1 ? b0k : b1k;
        myd += __shfl_xor_sync(0xffffffffu, cs, 1);

        // 3) tail: lane sub handles edge e0+sub (myr already resident)
        if (e < E && myr <= 4.0f) {
            int s  = src[e];
            int dn = dst[e];
            float4 ps = *(const float4*)(g_srcTab + (size_t)s * 8);
            float  gs = g_srcTab[(size_t)s * 8 + 4];
            float4 pd = *(const float4*)(g_dstTab + (size_t)dn * 8);
            float  gd = g_dstTab[(size_t)dn * 8 + 4];

            float m  = gs + gd + myd + begv;
            float bo = 1.0f / (1.0f + __expf(-m));

            float p1 = __expf(ps.y + pd.y);
            float p3 = __expf(ps.w + pd.w);
            // p0*exp(-p1*r) == exp(a0 - p1*r); same for attract term
            float frep = __expf(ps.x + pd.x - p1 * myr);
            float fatt = __expf(ps.z + pd.z - p3 * myr);

            // cutoff: 1 for r<3.8; 0.5-0.5*sin(pi*(r-3.9)/0.2) in [3.8,4.0]
            float c = 1.0f;
            if (myr >= 3.8f)
                c = 0.5f - 0.5f * __sinf(CUDART_PI_F * (myr - 3.9f) * 5.0f);

            float V = c * (frep - bo * fatt);
            atomicAdd(atom + dn, V);
            Vacc += V;
        }
    }

    // once per block: energy accumulation
#pragma unroll
    for (int off = 16; off >= 1; off >>= 1)
        Vacc += __shfl_xor_sync(0xffffffffu, Vacc, off);
    if ((tid & 31) == 0 && Vacc != 0.0f)
        atomicAdd(&sEsum, Vacc);
    __syncthreads();
    if (tid == 0)
        atomicAdd(out0, sEsum * invN);
}

extern "C" void kernel_launch(void* const* d_in, const int* in_sizes, int n_in,
                              void* d_out, int out_size)
{
    const float* x    = (const float*)d_in[0];
    const float* x0   = (const float*)d_in[1];
    const float* y    = (const float*)d_in[2];
    const float* bond = (const float*)d_in[3];
    const int*   src  = (const int*)d_in[4];
    const int*   dst  = (const int*)d_in[5];
    const float* Wsg  = (const float*)d_in[6];
    const float* bsg  = (const float*)d_in[7];
    const float* Wdg  = (const float*)d_in[8];
    const float* bdg  = (const float*)d_in[9];
    const float* Weg  = (const float*)d_in[10];
    const float* beg  = (const float*)d_in[11];
    const float* Wsp  = (const float*)d_in[12];
    const float* bsp  = (const float*)d_in[13];
    const float* Wdp  = (const float*)d_in[14];

    const int N = in_sizes[0] / HID;   // 50000
    const int E = in_sizes[3];         // 1600000

    float* out = (float*)d_out;        // out[0] = energy, out[1..N] = atomwise

    // 1) per-node gate/param precompute (smem-staged weights) + zero outputs
    node_kernel<<<(N * 8 + 255) / 256, 256>>>(x, x0, Wsg, bsg, Wdg, bdg,
                                              Wsp, bsp, Wdp, out + 1, out, N);

    // 2) persistent dense-stream edge kernel: 148 SMs x 5 blocks
    int nChunks = (E + 255) / 256;
    int grid = 148 * 5;
    if (grid > nChunks) grid = nChunks;
    edge_kernel<<<grid, 256>>>(y, bond, src, dst, Weg, beg, out + 1, out,
                               E, 1.0f / (float)N);
}

// round 17
// speedup vs baseline: 1.1173x; 1.1173x over previous
#include <cuda_runtime.h>
#include <math_constants.h>

#define HID   64
#define MAXN  50000

// Per-node precomputed tables, stride 8 floats for float4 alignment.
// srcTab[n*8 + 0..3] = ps (x0·Wsp + bsp), [n*8+4] = gs (x·Wsg + bsg)
// dstTab[n*8 + 0..3] = pd (x0·Wdp),       [n*8+4] = gd (x·Wdg + bdg)
__device__ float g_srcTab[MAXN * 8];
__device__ float g_dstTab[MAXN * 8];

// 8 lanes per node; smem-staged weights; butterfly transpose-reduce;
// distributed stores. Also zeroes the output accumulators.
__global__ void __launch_bounds__(256)
node_kernel(const float* __restrict__ x,
            const float* __restrict__ x0,
            const float* __restrict__ Wsg, const float* __restrict__ bsg,
            const float* __restrict__ Wdg, const float* __restrict__ bdg,
            const float* __restrict__ Wsp, const float* __restrict__ bsp,
            const float* __restrict__ Wdp,
            float* __restrict__ atom, float* __restrict__ out0,
            int n)
{
    __shared__ float sWsp[HID * 4];
    __shared__ float sWdp[HID * 4];
    __shared__ float sWsg[HID];
    __shared__ float sWdg[HID];

    const int tid = threadIdx.x;
    sWsp[tid] = Wsp[tid];
    sWdp[tid] = Wdp[tid];
    if (tid < HID) { sWsg[tid] = Wsg[tid]; sWdg[tid] = Wdg[tid]; }
    __syncthreads();

    int t    = blockIdx.x * blockDim.x + tid;
    int node = t >> 3;
    int sub  = t & 7;
    if (node >= n) return;

    const size_t base = (size_t)node * HID;
    const int h0 = sub * 4;
    const int h1 = 32 + sub * 4;

    float4 xa  = *(const float4*)(x  + base + h0);
    float4 xb  = *(const float4*)(x  + base + h1);
    float4 x0a = *(const float4*)(x0 + base + h0);
    float4 x0b = *(const float4*)(x0 + base + h1);

    float gs = 0.f, gd = 0.f;
    float v[8];
#pragma unroll
    for (int p = 0; p < 8; p++) v[p] = 0.f;

    const float* xav  = (const float*)&xa;
    const float* xbv  = (const float*)&xb;
    const float* x0av = (const float*)&x0a;
    const float* x0bv = (const float*)&x0b;

#pragma unroll
    for (int k = 0; k < 4; k++) {
        int ha = h0 + k, hb = h1 + k;
        gs += xav[k] * sWsg[ha] + xbv[k] * sWsg[hb];
        gd += xav[k] * sWdg[ha] + xbv[k] * sWdg[hb];
        float4 wsa = *(const float4*)(sWsp + ha * 4);
        float4 wsb = *(const float4*)(sWsp + hb * 4);
        float4 wda = *(const float4*)(sWdp + ha * 4);
        float4 wdb = *(const float4*)(sWdp + hb * 4);
        v[0] += x0av[k] * wsa.x + x0bv[k] * wsb.x;
        v[1] += x0av[k] * wsa.y + x0bv[k] * wsb.y;
        v[2] += x0av[k] * wsa.z + x0bv[k] * wsb.z;
        v[3] += x0av[k] * wsa.w + x0bv[k] * wsb.w;
        v[4] += x0av[k] * wda.x + x0bv[k] * wdb.x;
        v[5] += x0av[k] * wda.y + x0bv[k] * wdb.y;
        v[6] += x0av[k] * wda.z + x0bv[k] * wdb.z;
        v[7] += x0av[k] * wda.w + x0bv[k] * wdb.w;
    }

    bool hi4 = (sub & 4) != 0;
    float a0k = hi4 ? v[4] : v[0], a0s = hi4 ? v[0] : v[4];
    float a1k = hi4 ? v[5] : v[1], a1s = hi4 ? v[1] : v[5];
    float a2k = hi4 ? v[6] : v[2], a2s = hi4 ? v[2] : v[6];
    float a3k = hi4 ? v[7] : v[3], a3s = hi4 ? v[3] : v[7];
    a0k += __shfl_xor_sync(0xffffffffu, a0s, 4);
    a1k += __shfl_xor_sync(0xffffffffu, a1s, 4);
    a2k += __shfl_xor_sync(0xffffffffu, a2s, 4);
    a3k += __shfl_xor_sync(0xffffffffu, a3s, 4);
    bool hi2 = (sub & 2) != 0;
    float b0k = hi2 ? a2k : a0k, b0s = hi2 ? a0k : a2k;
    float b1k = hi2 ? a3k : a1k, b1s = hi2 ? a1k : a3k;
    b0k += __shfl_xor_sync(0xffffffffu, b0s, 2);
    b1k += __shfl_xor_sync(0xffffffffu, b1s, 2);
    bool hi1 = (sub & 1) != 0;
    float ck = hi1 ? b1k : b0k, cs = hi1 ? b0k : b1k;
    ck += __shfl_xor_sync(0xffffffffu, cs, 1);

#pragma unroll
    for (int off = 4; off >= 1; off >>= 1) {
        gs += __shfl_xor_sync(0xffffffffu, gs, off);
        gd += __shfl_xor_sync(0xffffffffu, gd, off);
    }

    if (sub < 4)
        g_srcTab[(size_t)node * 8 + sub] = ck + __ldg(bsp + sub);
    else
        g_dstTab[(size_t)node * 8 + (sub - 4)] = ck;
    if (sub == 0) {
        g_srcTab[(size_t)node * 8 + 4] = gs + __ldg(bsg);
        g_dstTab[(size_t)node * 8 + 4] = gd + __ldg(bdg);
        atom[node] = 0.0f;
        if (node == 0) *out0 = 0.0f;
    }
}

// Persistent edge kernel — BALLOT-GATED stream.
// Each lane loads ONE bond length (its own tail edge; coalesced, prefetched
// cross-iteration like the proven R8 pipeline). One __ballot_sync turns the
// 32 per-lane cutoff flags into a warp mask; y row p of 8-lane group g is
// gated by bit g*8+p. Keeps the 20% traffic skip with a dense-like body:
// no r[8] array, no per-row compares against prefetched data, 1/8th the
// bond loads. Tail self-contained except the pure myr prefetch rotation.
__global__ void __launch_bounds__(256, 5)
edge_kernel(const float* __restrict__ y,
            const float* __restrict__ bondlength,
            const int* __restrict__ src,
            const int* __restrict__ dst,
            const float* __restrict__ Weg,
            const float* __restrict__ beg,
            float* __restrict__ atom,
            float* __restrict__ out0,
            int E, float invN)
{
    __shared__ float sWeg[HID];
    __shared__ float sEsum;
    int tid = threadIdx.x;
    if (tid < HID) sWeg[tid] = Weg[tid];
    if (tid == 0)  sEsum = 0.0f;
    __syncthreads();

    const int sub      = tid & 7;
    const int lane     = tid & 31;
    const int grpInBlk = tid >> 3;             // 0..31
    const int bitBase  = lane & 24;            // 8*(group within warp)
    const float4 wa = *(const float4*)(sWeg + sub * 4);
    const float4 wb = *(const float4*)(sWeg + 32 + sub * 4);
    const float begv = __ldg(beg);

    const int CHUNK = 256;                     // edges per block-iteration
    const int nChunks = (E + CHUNK - 1) / CHUNK;

    float Vacc = 0.0f;
    int chunk = blockIdx.x;

    // prefetch this lane's bond length for the first chunk
    float myr = 5.0f;
    if (chunk < nChunks) {
        int e = chunk * CHUNK + grpInBlk * 8 + sub;
        myr = (e < E) ? __ldg(bondlength + e) : 5.0f;
    }

    for (; chunk < nChunks; chunk += gridDim.x) {
        const int e0 = chunk * CHUNK + grpInBlk * 8;
        const float* ybase = y + (size_t)e0 * HID;
        const int e = e0 + sub;

        // 0) warp-wide activity mask from resident myr (also covers e >= E)
        unsigned mask = __ballot_sync(0xffffffffu, myr <= 4.0f);

        // 1) y burst gated by mask bits: 8 rows x 2 contiguous 128B lines
        float d[8];
#pragma unroll
        for (int p = 0; p < 8; p++) {
            float da = 0.f;
            if ((mask >> (bitBase + p)) & 1u) {
                const float* row = ybase + (size_t)p * HID;
                float4 a = __ldcs((const float4*)(row + sub * 4));
                float4 b = __ldcs((const float4*)(row + 32 + sub * 4));
                da = a.x*wa.x + a.y*wa.y + a.z*wa.z + a.w*wa.w
                   + b.x*wb.x + b.y*wb.y + b.z*wb.z + b.w*wb.w;
            }
            d[p] = da;
        }

        // 2) prefetch NEXT chunk's bond length (pure load, rotated at end)
        float myr_next = 5.0f;
        {
            int nchunk = chunk + gridDim.x;
            if (nchunk < nChunks) {
                int ne = nchunk * CHUNK + grpInBlk * 8 + sub;
                myr_next = (ne < E) ? __ldg(bondlength + ne) : 5.0f;
            }
        }

        // 3) transpose-reduce: 7 shuffles; lane sub holds dot of edge e0+sub
        bool hi4 = (sub & 4) != 0;
        float a0k = hi4 ? d[4] : d[0], a0s = hi4 ? d[0] : d[4];
        float a1k = hi4 ? d[5] : d[1], a1s = hi4 ? d[1] : d[5];
        float a2k = hi4 ? d[6] : d[2], a2s = hi4 ? d[2] : d[6];
        float a3k = hi4 ? d[7] : d[3], a3s = hi4 ? d[3] : d[7];
        a0k += __shfl_xor_sync(0xffffffffu, a0s, 4);
        a1k += __shfl_xor_sync(0xffffffffu, a1s, 4);
        a2k += __shfl_xor_sync(0xffffffffu, a2s, 4);
        a3k += __shfl_xor_sync(0xffffffffu, a3s, 4);
        bool hi2 = (sub & 2) != 0;
        float b0k = hi2 ? a2k : a0k, b0s = hi2 ? a0k : a2k;
        float b1k = hi2 ? a3k : a1k, b1s = hi2 ? a1k : a3k;
        b0k += __shfl_xor_sync(0xffffffffu, b0s, 2);
        b1k += __shfl_xor_sync(0xffffffffu, b1s, 2);
        bool hi1 = (sub & 1) != 0;
        float myd = hi1 ? b1k : b0k, cs = hi1 ? b0k : b1k;
        myd += __shfl_xor_sync(0xffffffffu, cs, 1);

        // 4) tail: lane sub handles edge e0+sub (myr resident)
        if ((mask >> lane) & 1u) {       // myr <= 4 and (implicitly) e < E
            int s  = src[e];
            int dn = dst[e];
            float4 ps = *(const float4*)(g_srcTab + (size_t)s * 8);
            float  gs = g_srcTab[(size_t)s * 8 + 4];
            float4 pd = *(const float4*)(g_dstTab + (size_t)dn * 8);
            float  gd = g_dstTab[(size_t)dn * 8 + 4];

            float m  = gs + gd + myd + begv;
            float bo = 1.0f / (1.0f + __expf(-m));

            float p1 = __expf(ps.y + pd.y);
            float p3 = __expf(ps.w + pd.w);
            // p0*exp(-p1*r) == exp(a0 - p1*r); same for attract term
            float frep = __expf(ps.x + pd.x - p1 * myr);
            float fatt = __expf(ps.z + pd.z - p3 * myr);

            // cutoff: 1 for r<3.8; 0.5-0.5*sin(pi*(r-3.9)/0.2) in [3.8,4.0]
            float c = 1.0f;
            if (myr >= 3.8f)
                c = 0.5f - 0.5f * __sinf(CUDART_PI_F * (myr - 3.9f) * 5.0f);

            float V = c * (frep - bo * fatt);
            atomicAdd(atom + dn, V);
            Vacc += V;
        }

        myr = myr_next;
    }

    // once per block: energy accumulation
#pragma unroll
    for (int off = 16; off >= 1; off >>= 1)
        Vacc += __shfl_xor_sync(0xffffffffu, Vacc, off);
    if ((tid & 31) == 0 && Vacc != 0.0f)
        atomicAdd(&sEsum, Vacc);
    __syncthreads();
    if (tid == 0)
        atomicAdd(out0, sEsum * invN);
}

extern "C" void kernel_launch(void* const* d_in, const int* in_sizes, int n_in,
                              void* d_out, int out_size)
{
    const float* x    = (const float*)d_in[0];
    const float* x0   = (const float*)d_in[1];
    const float* y    = (const float*)d_in[2];
    const float* bond = (const float*)d_in[3];
    const int*   src  = (const int*)d_in[4];
    const int*   dst  = (const int*)d_in[5];
    const float* Wsg  = (const float*)d_in[6];
    const float* bsg  = (const float*)d_in[7];
    const float* Wdg  = (const float*)d_in[8];
    const float* bdg  = (const float*)d_in[9];
    const float* Weg  = (const float*)d_in[10];
    const float* beg  = (const float*)d_in[11];
    const float* Wsp  = (const float*)d_in[12];
    const float* bsp  = (const float*)d_in[13];
    const float* Wdp  = (const float*)d_in[14];

    const int N = in_sizes[0] / HID;   // 50000
    const int E = in_sizes[3];         // 1600000

    float* out = (float*)d_out;        // out[0] = energy, out[1..N] = atomwise

    // 1) per-node gate/param precompute (smem-staged weights) + zero outputs
    node_kernel<<<(N * 8 + 255) / 256, 256>>>(x, x0, Wsg, bsg, Wdg, bdg,
                                              Wsp, bsp, Wdp, out + 1, out, N);

    // 2) persistent ballot-gated edge kernel: 148 SMs x 5 blocks
    int nChunks = (E + 255) / 256;
    int grid = 148 * 5;
    if (grid > nChunks) grid = nChunks;
    edge_kernel<<<grid, 256>>>(y, bond, src, dst, Weg, beg, out + 1, out,
                               E, 1.0f / (float)N);
}